// round 5
// baseline (speedup 1.0000x reference)
#include <cuda_runtime.h>
#include <math.h>
#include <stdint.h>

// Problem constants
#define NB   16      // batch
#define NPTS 512     // points per sample
#define MS   4096    // m = 64*64 grid cells
#define NIT  100     // ASGD iterations
#define NCHUNK 16    // wd chunks per sample (rows per block = 32)

// Scratch (device globals; no allocation allowed)
__device__ float g_w[NB * MS];      // beta + 10*log(b), per sample
__device__ float g_wmax[NB];
__device__ float g_loss[NB];
__device__ float g_ot[NB];
__device__ float g_wd[NB * NCHUNK];
__device__ unsigned int g_ctr;      // last-block counter for fused finalize

// ---------------------------------------------------------------------------
// Threefry2x32, JAX partitionable path (verified passing):
//   k2 = tf((0,1), (0,1));  idx[t] = (y0^y1 of tf(k2, (0,t))) & 511
// ---------------------------------------------------------------------------
__device__ __forceinline__ uint32_t rotl32(uint32_t x, int r) {
    return (x << r) | (x >> (32 - r));
}

__device__ __forceinline__ void tf2x32(uint32_t k0, uint32_t k1,
                                       uint32_t& x0, uint32_t& x1) {
    uint32_t ks2 = 0x1BD11BDAu ^ k0 ^ k1;
    x0 += k0; x1 += k1;
#define TF_RND(r) { x0 += x1; x1 = rotl32(x1, r); x1 ^= x0; }
    TF_RND(13) TF_RND(15) TF_RND(26) TF_RND(6)
    x0 += k1;  x1 += ks2 + 1u;
    TF_RND(17) TF_RND(29) TF_RND(16) TF_RND(24)
    x0 += ks2; x1 += k0 + 2u;
    TF_RND(13) TF_RND(15) TF_RND(26) TF_RND(6)
    x0 += k0;  x1 += k1 + 3u;
    TF_RND(17) TF_RND(29) TF_RND(16) TF_RND(24)
    x0 += k1;  x1 += ks2 + 4u;
    TF_RND(13) TF_RND(15) TF_RND(26) TF_RND(6)
    x0 += ks2; x1 += k0 + 5u;
#undef TF_RND
}

// ---------------------------------------------------------------------------
// Block reduction (512 threads): two-level shfl, all threads get result.
// op: 0 = sum, 1 = max. Internally double-synced so calls can be chained.
// ---------------------------------------------------------------------------
__device__ __forceinline__ float blk_red(float v, float* sred, int op) {
    const int tid = threadIdx.x, lane = tid & 31, wid = tid >> 5;
    #pragma unroll
    for (int o = 16; o > 0; o >>= 1) {
        float t = __shfl_xor_sync(0xffffffffu, v, o);
        v = op ? fmaxf(v, t) : (v + t);
    }
    __syncthreads();
    if (lane == 0) sred[wid] = v;
    __syncthreads();
    float u = sred[lane & 15];
    #pragma unroll
    for (int o = 8; o > 0; o >>= 1) {
        float t = __shfl_xor_sync(0xffffffffu, u, o);
        u = op ? fmaxf(u, t) : (u + t);
    }
    return u;
}

// ---------------------------------------------------------------------------
// Scan kernel: one block per sample. Init by 512 threads; the 100 sequential
// ASGD iterations run on WARP 0 ONLY over a pruned active region; untouched
// cells evolve in closed form via lazy {P, S, last} bookkeeping in smem.
//   cur_j(k) = P_j(k) + b_j * C_k,   C_k = sum_{m<=k} c_m
//   ave_100  = (S_total_j + b_j * sum_l C_l) / 100
// Region at iter k (point (px,py), own cell j*):
//   include j if M_ij <= 10*(U - z*) + 300, U >= max_j u_j (maintained bound)
// Stabilizer m = z* + max(0, (U - z*) - 70)  (softmax is m-invariant).
// ---------------------------------------------------------------------------
#define OFF_PS   0        // float2[4096]  (P, S)
#define OFF_B    32768    // float[4096]
#define OFF_LB   49152    // float[4096]
#define OFF_LAST 65536    // float[4096]
#define OFF_SPT  81920    // float[200]
#define OFF_RED  82752    // float[32]
#define OFF_SCAL 82880    // float[4]
#define SMEM_SCAN 82944

__global__ void __launch_bounds__(512, 1)
k_scan(const float* __restrict__ normed, const float* __restrict__ unnormed,
       const float* __restrict__ pts) {
    extern __shared__ char smem_raw[];
    float2* PS   = (float2*)(smem_raw + OFF_PS);
    float*  BV   = (float*) (smem_raw + OFF_B);
    float*  LB   = (float*) (smem_raw + OFF_LB);
    float*  LAST = (float*) (smem_raw + OFF_LAST);
    float*  SPT  = (float*) (smem_raw + OFF_SPT);
    float*  SRED = (float*) (smem_raw + OFF_RED);
    float*  SCAL = (float*) (smem_raw + OFF_SCAL);

    const int s   = blockIdx.x;
    const int tid = threadIdx.x;
    const int lane = tid & 31;

    const float* bp = normed   + s * MS;
    const float* up = unnormed + s * MS;
    const float* pp = pts      + s * NPTS * 2;

    // ---- Init: fill smem state, gather iteration points, reduce bmax/maxlb
    float bmax_l = -INFINITY, lmax_l = -INFINITY;
    #pragma unroll
    for (int t = 0; t < 8; t++) {
        int j = tid + t * 512;
        float b = bp[j];
        float lbv = logf(b);
        BV[j] = b; LB[j] = lbv;
        PS[j] = make_float2(0.0f, 0.0f);
        LAST[j] = 0.0f;
        bmax_l = fmaxf(bmax_l, b);
        lmax_l = fmaxf(lmax_l, lbv);
    }
    if (tid < NIT) {
        uint32_t c0 = 0u, c1 = 1u;
        tf2x32(0u, 1u, c0, c1);               // k2
        uint32_t x0 = 0u, x1 = (uint32_t)(s * NIT + tid);
        tf2x32(c0, c1, x0, x1);
        int i = (int)((x0 ^ x1) & 511u);
        SPT[2 * tid]     = pp[2 * i];
        SPT[2 * tid + 1] = pp[2 * i + 1];
    }
    float bmax  = blk_red(bmax_l, SRED, 1);
    float maxlb = blk_red(lmax_l, SRED, 1);
    __syncthreads();

    // ---- Sequential ASGD on warp 0 only (no block barriers inside) ----
    if (tid < 32) {
        float U = maxlb;     // upper bound on u_j = cur_j/10 + lb_j
        float C = 0.0f;      // C_{k-1}
        float SC = 0.0f;     // sum_{l<=k} C_l

        for (int k = 1; k <= NIT; k++) {
            float ck = 5120.0f / sqrtf((float)k);
            float px = SPT[2 * k - 2], py = SPT[2 * k - 1];

            // point's own cell -> z*, stabilizer, region bounds
            int jxs = (int)(px * 0.125f);
            int jys = (int)(py * 0.125f);
            int js  = jys * 64 + jxs;
            float dxs = px - (float)(jxs * 8 + 4);
            float dys = py - (float)(jys * 8 + 4);
            float Ms  = dxs * dxs + dys * dys;
            float2 pss = PS[js];
            float zs = (pss.x + BV[js] * C - Ms) * 0.1f + LB[js];
            float D  = U - zs;                       // >= 0
            float m  = zs + fmaxf(0.0f, D - 70.0f);  // overflow-safe stabilizer
            float T  = 10.0f * D + 300.0f;           // region: M <= T
            float xr = sqrtf(T);
            int jxlo = max(0,  (int)ceilf ((px - xr - 4.0f) * 0.125f));
            int jxhi = min(63, (int)floorf((px + xr - 4.0f) * 0.125f));
            int jylo = max(0,  (int)ceilf ((py - xr - 4.0f) * 0.125f));
            int jyhi = min(63, (int)floorf((py + xr - 4.0f) * 0.125f));

            // pass 1: sum of exp over region
            float se = 0.0f;
            for (int jy = jylo; jy <= jyhi; jy++) {
                float dy = py - (float)(jy * 8 + 4);
                float yd = dy * dy;
                for (int jx = jxlo + lane; jx <= jxhi; jx += 32) {
                    float dx = px - (float)(jx * 8 + 4);
                    int j = jy * 64 + jx;
                    float2 ps = PS[j];
                    float z = (ps.x + BV[j] * C - (yd + dx * dx)) * 0.1f + LB[j];
                    se += __expf(z - m);
                }
            }
            #pragma unroll
            for (int o = 16; o > 0; o >>= 1)
                se += __shfl_xor_sync(0xffffffffu, se, o);
            float inv = 1.0f / se;

            // pass 2: khi correction + lazy S/last update for region cells
            float km1 = (float)(k - 1);
            for (int jy = jylo; jy <= jyhi; jy++) {
                float dy = py - (float)(jy * 8 + 4);
                float yd = dy * dy;
                for (int jx = jxlo + lane; jx <= jxhi; jx += 32) {
                    float dx = px - (float)(jx * 8 + 4);
                    int j = jy * 64 + jx;
                    float2 ps = PS[j];
                    float z = (ps.x + BV[j] * C - (yd + dx * dx)) * 0.1f + LB[j];
                    float khi = __expf(z - m) * inv;
                    float Pn = ps.x - ck * khi;
                    float Sn = ps.y + ps.x * (km1 - LAST[j]) + Pn;
                    PS[j] = make_float2(Pn, Sn);
                    LAST[j] = (float)k;
                }
            }

            C += ck;
            SC += C;
            U += ck * bmax * 0.1f;
        }
        if (lane == 0) SCAL[0] = SC;
    }
    __syncthreads();

    // ---- Epilogue (all 512 threads): materialize ave, w; reductions ----
    float SC01 = SCAL[0] * 0.01f;
    float aveR[8], srcR[8];
    float p_ot = 0.0f, p_sc = 0.0f, p_td = 0.0f, wmx = -INFINITY;
    #pragma unroll
    for (int t = 0; t < 8; t++) {
        int j = tid + t * 512;
        float2 ps = PS[j];
        float b = BV[j], lbv = LB[j], la = LAST[j];
        float ave = (ps.y + ps.x * (100.0f - la)) * 0.01f + b * SC01;
        float w = ave + 10.0f * lbv;
        g_w[s * MS + j] = w;
        float src = up[j];
        aveR[t] = ave; srcR[t] = src;
        p_ot += b * ave;
        p_sc += src;
        p_td += src * ave;
        wmx = fmaxf(wmx, w);
    }
    float ot = blk_red(p_ot, SRED, 0);
    float sc = blk_red(p_sc, SRED, 0);
    float td = blk_red(p_td, SRED, 0);
    float wm = blk_red(wmx, SRED, 1);
    float denom = sc * sc + 1e-16f;
    float q1 = sc / denom, q2 = td / denom;
    float p_ls = 0.0f;
    #pragma unroll
    for (int t = 0; t < 8; t++) p_ls += srcR[t] * (q1 * aveR[t] - q2);
    float ls = blk_red(p_ls, SRED, 0);
    if (tid == 0) {
        g_ot[s] = ot;
        g_loss[s] = ls;
        g_wmax[s] = wm;
        if (s == 0) g_ctr = 0;   // reset finalize counter (pre-k_wd in stream)
    }
}

// ---------------------------------------------------------------------------
// wd kernel with analytic pruning: per row i, softmax weights of (w - M)/10
// concentrate near the point; stabilizer from the point's own cell + wmax.
// Region: M <= (wmax - raw*) + 350. grid (16 chunks, 16 samples), 256 thr.
// Last block (atomic counter) performs the deterministic finalize.
// ---------------------------------------------------------------------------
__global__ void __launch_bounds__(256)
k_wd(const float* __restrict__ pts, float* __restrict__ out) {
    const int s = blockIdx.y;
    const int chunk = blockIdx.x;
    const int tid = threadIdx.x;
    const int wid = tid >> 5, lane = tid & 31;
    __shared__ float sw[MS];
    __shared__ float wacc[8];
    __shared__ unsigned int sflag;

    for (int j = tid; j < MS; j += 256)
        sw[j] = g_w[s * MS + j];
    const float wmax = g_wmax[s];
    __syncthreads();

    const float* pp = pts + s * NPTS * 2;
    float acc = 0.0f;

    #pragma unroll
    for (int rr = 0; rr < 4; rr++) {
        int i = chunk * 32 + wid * 4 + rr;
        float px = pp[2 * i], py = pp[2 * i + 1];

        int jxs = (int)(px * 0.125f);
        int jys = (int)(py * 0.125f);
        int js  = jys * 64 + jxs;
        float dxs = px - (float)(jxs * 8 + 4);
        float dys = py - (float)(jys * 8 + 4);
        float Ms  = dxs * dxs + dys * dys;
        float raws = sw[js] - Ms;              // raw units (= 10*z at j*)
        float D10 = wmax - raws;               // >= -Ms >= -32; clamp at 0
        float m = raws * 0.1f + fmaxf(0.0f, D10 * 0.1f - 70.0f);
        float T = fmaxf(D10, 0.0f) + 350.0f;
        float xr = sqrtf(T);
        int jxlo = max(0,  (int)ceilf ((px - xr - 4.0f) * 0.125f));
        int jxhi = min(63, (int)floorf((px + xr - 4.0f) * 0.125f));
        int jylo = max(0,  (int)ceilf ((py - xr - 4.0f) * 0.125f));
        int jyhi = min(63, (int)floorf((py + xr - 4.0f) * 0.125f));

        float se = 0.0f, st = 0.0f;
        for (int jy = jylo; jy <= jyhi; jy++) {
            float dy = py - (float)(jy * 8 + 4);
            float yd = dy * dy;
            for (int jx = jxlo + lane; jx <= jxhi; jx += 32) {
                float dx = px - (float)(jx * 8 + 4);
                float M = yd + dx * dx;
                int j = jy * 64 + jx;
                float e = __expf((sw[j] - M) * 0.1f - m);
                se += e;
                st += e * M;
            }
        }
        #pragma unroll
        for (int o = 16; o > 0; o >>= 1) {
            se += __shfl_xor_sync(0xffffffffu, se, o);
            st += __shfl_xor_sync(0xffffffffu, st, o);
        }
        acc += st / se;
    }
    if (lane == 0) wacc[wid] = acc;
    __syncthreads();
    if (tid == 0) {
        float t = 0.0f;
        #pragma unroll
        for (int w = 0; w < 8; w++) t += wacc[w];
        g_wd[s * NCHUNK + chunk] = t * (1.0f / 512.0f);
        __threadfence();
        unsigned int old = atomicAdd(&g_ctr, 1u);
        sflag = (old == (NB * NCHUNK - 1)) ? 1u : 0u;
    }
    __syncthreads();

    // ---- Fused finalize by the last block (fixed-order sums: deterministic)
    if (sflag) {
        // wd: 256 partials, one per thread
        float v = g_wd[tid];
        #pragma unroll
        for (int o = 16; o > 0; o >>= 1)
            v += __shfl_xor_sync(0xffffffffu, v, o);
        if (lane == 0) wacc[wid] = v;
        __syncthreads();
        if (tid == 0) {
            float W = 0.0f;
            #pragma unroll
            for (int w = 0; w < 8; w++) W += wacc[w];
            float L = 0.0f, O = 0.0f;
            for (int q = 0; q < NB; q++) { L += g_loss[q]; O += g_ot[q]; }
            out[0] = L; out[1] = W; out[2] = O;
        }
    }
}

extern "C" void kernel_launch(void* const* d_in, const int* in_sizes, int n_in,
                              void* d_out, int out_size) {
    const float* normed   = (const float*)d_in[0];
    const float* unnormed = (const float*)d_in[1];
    const float* pts      = (const float*)d_in[2];
    float* out = (float*)d_out;

    cudaFuncSetAttribute(k_scan, cudaFuncAttributeMaxDynamicSharedMemorySize,
                         SMEM_SCAN);
    k_scan<<<NB, 512, SMEM_SCAN>>>(normed, unnormed, pts);
    dim3 g(NCHUNK, NB);
    k_wd<<<g, 256>>>(pts, out);
}

// round 9
// speedup vs baseline: 2.0054x; 2.0054x over previous
#include <cuda_runtime.h>
#include <math.h>
#include <stdint.h>

// Problem constants
#define NB   16      // batch
#define NPTS 512     // points per sample
#define MS   4096    // m = 64*64 grid cells
#define NIT  100     // ASGD iterations
#define NCHUNK 16    // wd chunks per sample (32 rows per block)
#define S_EXP 0.14426950408889634f   // 0.1 * log2(e)

// Scratch (device globals; no allocation allowed)
__device__ float g_w[NB * MS];      // beta + 10*log(b), per sample
__device__ float g_wmax[NB];
__device__ float g_loss[NB];
__device__ float g_ot[NB];
__device__ float g_wd[NB * NCHUNK];
__device__ unsigned int g_ctr;      // last-block counter for fused finalize

// ---------------------------------------------------------------------------
// Threefry2x32, JAX partitionable path (verified passing):
//   k2 = tf((0,1), (0,1));  idx[t] = (y0^y1 of tf(k2, (0,t))) & 511
// ---------------------------------------------------------------------------
__device__ __forceinline__ uint32_t rotl32(uint32_t x, int r) {
    return (x << r) | (x >> (32 - r));
}

__device__ __forceinline__ void tf2x32(uint32_t k0, uint32_t k1,
                                       uint32_t& x0, uint32_t& x1) {
    uint32_t ks2 = 0x1BD11BDAu ^ k0 ^ k1;
    x0 += k0; x1 += k1;
#define TF_RND(r) { x0 += x1; x1 = rotl32(x1, r); x1 ^= x0; }
    TF_RND(13) TF_RND(15) TF_RND(26) TF_RND(6)
    x0 += k1;  x1 += ks2 + 1u;
    TF_RND(17) TF_RND(29) TF_RND(16) TF_RND(24)
    x0 += ks2; x1 += k0 + 2u;
    TF_RND(13) TF_RND(15) TF_RND(26) TF_RND(6)
    x0 += k0;  x1 += k1 + 3u;
    TF_RND(17) TF_RND(29) TF_RND(16) TF_RND(24)
    x0 += k1;  x1 += ks2 + 4u;
    TF_RND(13) TF_RND(15) TF_RND(26) TF_RND(6)
    x0 += ks2; x1 += k0 + 5u;
#undef TF_RND
}

// Block reduction (512 threads), all threads get result. op: 0=sum, 1=max.
__device__ __forceinline__ float blk_red(float v, float* sred, int op) {
    const int tid = threadIdx.x, lane = tid & 31, wid = tid >> 5;
    #pragma unroll
    for (int o = 16; o > 0; o >>= 1) {
        float t = __shfl_xor_sync(0xffffffffu, v, o);
        v = op ? fmaxf(v, t) : (v + t);
    }
    __syncthreads();
    if (lane == 0) sred[wid] = v;
    __syncthreads();
    float u = sred[lane & 15];
    #pragma unroll
    for (int o = 8; o > 0; o >>= 1) {
        float t = __shfl_xor_sync(0xffffffffu, u, o);
        u = op ? fmaxf(u, t) : (u + t);
    }
    return u;
}

// ---------------------------------------------------------------------------
// Dense scan kernel (exact algorithm, no pruning): one block per sample,
// 512 threads, 8 cells/thread in registers.
// State zb = cur/10 + lb;  z_ij = zb - M_ij/10;  khi = softmax(z).
// Update: zb += 0.1*ck*(b - khi).  ave tracked via sb = sum_k zb_k:
//   ave = 0.1*sb - 10*lb,   w = ave + 10*lb = 0.1*sb.
// Two barriers/iter (max-phase, sum-phase); single-buffer smem is race-free
// because each array's reads complete before any thread can pass the barrier
// that precedes the next write to it.
// ---------------------------------------------------------------------------
__global__ void __launch_bounds__(512, 1)
k_scan(const float* __restrict__ normed, const float* __restrict__ unnormed,
       const float* __restrict__ pts) {
    __shared__ float2 SPT[NIT];
    __shared__ float  SCK[NIT];     // 0.1 * 5120 / sqrt(k+1)
    __shared__ float  SMX[16], SSM[16], SRED[16];

    const int s   = blockIdx.x;
    const int tid = threadIdx.x;
    const int lane = tid & 31;
    const int wid  = tid >> 5;

    const float* bp = normed   + s * MS;
    const float* up = unnormed + s * MS;
    const float* pp = pts      + s * NPTS * 2;

    // per-thread geometry: column fixed, rows step by 64 units
    const float cx  = (float)((tid & 63) * 8 + 4);
    const float cy0 = (float)((tid >> 6) * 8 + 4);

    float b[8], zb[8], sb[8];
    #pragma unroll
    for (int t = 0; t < 8; t++) {
        int j = tid + t * 512;
        b[t]  = bp[j];
        zb[t] = __logf(b[t]);       // zb_0 = lb
        sb[t] = 0.0f;
    }

    if (tid < NIT) {
        uint32_t c0 = 0u, c1 = 1u;
        tf2x32(0u, 1u, c0, c1);               // k2
        uint32_t x0 = 0u, x1 = (uint32_t)(s * NIT + tid);
        tf2x32(c0, c1, x0, x1);
        int i = (int)((x0 ^ x1) & 511u);
        SPT[tid] = make_float2(pp[2 * i], pp[2 * i + 1]);
        SCK[tid] = __fdividef(512.0f, sqrtf((float)(tid + 1)));
    }
    __syncthreads();

    for (int k = 0; k < NIT; k++) {
        float2 p = SPT[k];
        float ck10 = SCK[k];
        float dx  = p.x - cx;
        float dx2 = dx * dx;
        float dyb = p.y - cy0;

        // ---- Phase A: z + block max ----
        float z[8];
        float mx = -INFINITY;
        #pragma unroll
        for (int t = 0; t < 8; t++) {
            float dy = dyb - (float)(64 * t);
            float md = fmaf(dy, dy, dx2);
            z[t] = fmaf(md, -0.1f, zb[t]);
            mx = fmaxf(mx, z[t]);
        }
        #pragma unroll
        for (int o = 16; o > 0; o >>= 1)
            mx = fmaxf(mx, __shfl_xor_sync(0xffffffffu, mx, o));
        if (lane == 0) SMX[wid] = mx;
        __syncthreads();
        float gm = SMX[lane & 15];
        #pragma unroll
        for (int o = 8; o > 0; o >>= 1)
            gm = fmaxf(gm, __shfl_xor_sync(0xffffffffu, gm, o));

        // ---- Phase B: exp + block sum ----
        float e[8];
        float se = 0.0f;
        #pragma unroll
        for (int t = 0; t < 8; t++) {
            e[t] = exp2f((z[t] - gm) * (10.0f * S_EXP));
            se += e[t];
        }
        #pragma unroll
        for (int o = 16; o > 0; o >>= 1)
            se += __shfl_xor_sync(0xffffffffu, se, o);
        if (lane == 0) SSM[wid] = se;
        __syncthreads();
        float bs = SSM[lane & 15];
        #pragma unroll
        for (int o = 8; o > 0; o >>= 1)
            bs += __shfl_xor_sync(0xffffffffu, bs, o);

        // ---- Update ----
        float inv = __fdividef(1.0f, bs);
        #pragma unroll
        for (int t = 0; t < 8; t++) {
            zb[t] = fmaf(ck10, b[t] - e[t] * inv, zb[t]);
            sb[t] += zb[t];
        }
    }

    // ---- Epilogue: w = 0.1*sb; ave = w - 10*lb; reductions ----
    float aveR[8], srcR[8];
    float p_ot = 0.0f, p_sc = 0.0f, p_td = 0.0f, wmx = -INFINITY;
    #pragma unroll
    for (int t = 0; t < 8; t++) {
        int j = tid + t * 512;
        float w = 0.1f * sb[t];
        float ave = w - 10.0f * __logf(b[t]);
        g_w[s * MS + j] = w;
        float src = up[j];
        aveR[t] = ave; srcR[t] = src;
        p_ot += b[t] * ave;
        p_sc += src;
        p_td += src * ave;
        wmx = fmaxf(wmx, w);
    }
    float ot = blk_red(p_ot, SRED, 0);
    float sc = blk_red(p_sc, SRED, 0);
    float td = blk_red(p_td, SRED, 0);
    float wm = blk_red(wmx, SRED, 1);
    float denom = sc * sc + 1e-16f;
    float q1s = sc / denom, q2s = td / denom;
    float p_ls = 0.0f;
    #pragma unroll
    for (int t = 0; t < 8; t++) p_ls += srcR[t] * (q1s * aveR[t] - q2s);
    float ls = blk_red(p_ls, SRED, 0);
    if (tid == 0) {
        g_ot[s] = ot;
        g_loss[s] = ls;
        g_wmax[s] = wm;
        if (s == 0) g_ctr = 0;
    }
}

// ---------------------------------------------------------------------------
// wd kernel (R5 adaptive version — verified correct): per row i, softmax of
// (w - M)/10 concentrates near the point; stabilizer anchored at own cell
// with wmax overflow guard; adaptive region M <= (wmax - raw*) + 350.
// grid (16 chunks, 16 samples), 256 threads. Last block does the finalize.
// ---------------------------------------------------------------------------
__global__ void __launch_bounds__(256)
k_wd(const float* __restrict__ pts, float* __restrict__ out) {
    const int s = blockIdx.y;
    const int chunk = blockIdx.x;
    const int tid = threadIdx.x;
    const int wid = tid >> 5, lane = tid & 31;
    __shared__ float sw[MS];
    __shared__ float wacc[8];
    __shared__ unsigned int sflag;

    for (int j = tid; j < MS; j += 256)
        sw[j] = g_w[s * MS + j];
    const float wmax = g_wmax[s];
    __syncthreads();

    const float* pp = pts + s * NPTS * 2;
    float acc = 0.0f;

    #pragma unroll
    for (int rr = 0; rr < 4; rr++) {
        int i = chunk * 32 + wid * 4 + rr;
        float px = pp[2 * i], py = pp[2 * i + 1];

        int jxs = (int)(px * 0.125f);
        int jys = (int)(py * 0.125f);
        int js  = jys * 64 + jxs;
        float dxs = px - (float)(jxs * 8 + 4);
        float dys = py - (float)(jys * 8 + 4);
        float Ms  = dxs * dxs + dys * dys;
        float raws = sw[js] - Ms;              // raw units
        float D10 = wmax - raws;
        float m = raws * 0.1f + fmaxf(0.0f, D10 * 0.1f - 70.0f);
        float T = fmaxf(D10, 0.0f) + 350.0f;
        float xr = sqrtf(T);
        int jxlo = max(0,  (int)ceilf ((px - xr - 4.0f) * 0.125f));
        int jxhi = min(63, (int)floorf((px + xr - 4.0f) * 0.125f));
        int jylo = max(0,  (int)ceilf ((py - xr - 4.0f) * 0.125f));
        int jyhi = min(63, (int)floorf((py + xr - 4.0f) * 0.125f));

        float se = 0.0f, st = 0.0f;
        for (int jy = jylo; jy <= jyhi; jy++) {
            float dy = py - (float)(jy * 8 + 4);
            float yd = dy * dy;
            for (int jx = jxlo + lane; jx <= jxhi; jx += 32) {
                float dx = px - (float)(jx * 8 + 4);
                float M = yd + dx * dx;
                int j = jy * 64 + jx;
                float e = __expf((sw[j] - M) * 0.1f - m);
                se += e;
                st += e * M;
            }
        }
        #pragma unroll
        for (int o = 16; o > 0; o >>= 1) {
            se += __shfl_xor_sync(0xffffffffu, se, o);
            st += __shfl_xor_sync(0xffffffffu, st, o);
        }
        se = fmaxf(se, 1e-30f);   // dormant guard (never triggers in practice)
        acc += st / se;
    }
    if (lane == 0) wacc[wid] = acc;
    __syncthreads();
    if (tid == 0) {
        float t = 0.0f;
        #pragma unroll
        for (int w = 0; w < 8; w++) t += wacc[w];
        g_wd[s * NCHUNK + chunk] = t * (1.0f / 512.0f);
        __threadfence();
        unsigned int old = atomicAdd(&g_ctr, 1u);
        sflag = (old == (NB * NCHUNK - 1)) ? 1u : 0u;
    }
    __syncthreads();

    // ---- Fused finalize by the last block (fixed-order: deterministic) ----
    if (sflag) {
        float v = g_wd[tid];
        #pragma unroll
        for (int o = 16; o > 0; o >>= 1)
            v += __shfl_xor_sync(0xffffffffu, v, o);
        if (lane == 0) wacc[wid] = v;
        __syncthreads();
        if (tid == 0) {
            float W = 0.0f;
            #pragma unroll
            for (int w = 0; w < 8; w++) W += wacc[w];
            float L = 0.0f, O = 0.0f;
            for (int q = 0; q < NB; q++) { L += g_loss[q]; O += g_ot[q]; }
            out[0] = L; out[1] = W; out[2] = O;
        }
    }
}

extern "C" void kernel_launch(void* const* d_in, const int* in_sizes, int n_in,
                              void* d_out, int out_size) {
    const float* normed   = (const float*)d_in[0];
    const float* unnormed = (const float*)d_in[1];
    const float* pts      = (const float*)d_in[2];
    float* out = (float*)d_out;

    k_scan<<<NB, 512>>>(normed, unnormed, pts);
    dim3 g(NCHUNK, NB);
    k_wd<<<g, 256>>>(pts, out);
}

// round 14
// speedup vs baseline: 2.6056x; 1.2993x over previous
#include <cuda_runtime.h>
#include <math.h>
#include <stdint.h>

// Problem constants
#define NB   16      // batch
#define NPTS 512     // points per sample
#define MS   4096    // m = 64*64 grid cells
#define NIT  100     // ASGD iterations
#define NCH  32      // wd chunks per sample (16 rows per block)
#define L2E  1.44269504088896f   // log2(e)

// Scratch (device globals; no allocation allowed)
__device__ float g_w[NB * MS];      // beta + 10*log(b), per sample
__device__ float g_wmax[NB];
__device__ float g_loss[NB];
__device__ float g_ot[NB];
__device__ float g_wd[NB * NCH];
__device__ unsigned int g_ctr;      // last-block counter for fused finalize

// ---------------------------------------------------------------------------
// Threefry2x32, JAX partitionable path (verified passing):
//   k2 = tf((0,1), (0,1));  idx[t] = (y0^y1 of tf(k2, (0,t))) & 511
// ---------------------------------------------------------------------------
__device__ __forceinline__ uint32_t rotl32(uint32_t x, int r) {
    return (x << r) | (x >> (32 - r));
}

__device__ __forceinline__ void tf2x32(uint32_t k0, uint32_t k1,
                                       uint32_t& x0, uint32_t& x1) {
    uint32_t ks2 = 0x1BD11BDAu ^ k0 ^ k1;
    x0 += k0; x1 += k1;
#define TF_RND(r) { x0 += x1; x1 = rotl32(x1, r); x1 ^= x0; }
    TF_RND(13) TF_RND(15) TF_RND(26) TF_RND(6)
    x0 += k1;  x1 += ks2 + 1u;
    TF_RND(17) TF_RND(29) TF_RND(16) TF_RND(24)
    x0 += ks2; x1 += k0 + 2u;
    TF_RND(13) TF_RND(15) TF_RND(26) TF_RND(6)
    x0 += k0;  x1 += k1 + 3u;
    TF_RND(17) TF_RND(29) TF_RND(16) TF_RND(24)
    x0 += k1;  x1 += ks2 + 4u;
    TF_RND(13) TF_RND(15) TF_RND(26) TF_RND(6)
    x0 += ks2; x1 += k0 + 5u;
#undef TF_RND
}

// Block reduction for 256 threads (8 warps). op: 0=sum, 1=max.
__device__ __forceinline__ float blk_red8(float v, float* sred, int op) {
    const int tid = threadIdx.x, lane = tid & 31, wid = tid >> 5;
    #pragma unroll
    for (int o = 16; o > 0; o >>= 1) {
        float t = __shfl_xor_sync(0xffffffffu, v, o);
        v = op ? fmaxf(v, t) : (v + t);
    }
    __syncthreads();
    if (lane == 0) sred[wid] = v;
    __syncthreads();
    float u = sred[lane & 7];
    #pragma unroll
    for (int o = 4; o > 0; o >>= 1) {
        float t = __shfl_xor_sync(0xffffffffu, u, o);
        u = op ? fmaxf(u, t) : (u + t);
    }
    return u;
}

// ---------------------------------------------------------------------------
// Dense scan kernel: one block per sample, 256 threads, 16 cells/thread.
// Warp w owns the 64x8-cell slab rows [8w, 8w+8); thread = 2 cols x 8 rows.
// State zb = cur/10 + lb;  z_ij = zb - M_ij/10;  khi = softmax(z) (exact).
// Phase A: block max (no MUFU). Phase B: per-warp underflow skip — if the
// warp's own max is < gm-88, all its exp contributions are < 1e-38 and are
// replaced by 0 (exact to fp noise); update khi=0 path is 1 fma/cell.
// ---------------------------------------------------------------------------
__global__ void __launch_bounds__(256, 1)
k_scan(const float* __restrict__ normed, const float* __restrict__ unnormed,
       const float* __restrict__ pts) {
    __shared__ float2 SPT[NIT];
    __shared__ float  SCK[NIT];
    __shared__ __align__(16) float SMX[8];
    __shared__ __align__(16) float SSM[8];
    __shared__ __align__(16) float SRED[8];

    const int s    = blockIdx.x;
    const int tid  = threadIdx.x;
    const int lane = tid & 31;
    const int wid  = tid >> 5;          // 0..7

    const float2* bp2 = (const float2*)(normed + s * MS);
    const float*  up  = unnormed + s * MS;
    const float*  pp  = pts      + s * NPTS * 2;

    // thread cells: x in {32*? } -> pair index = lane (cols 2*lane, 2*lane+1),
    // rows y = 8*wid + t, t = 0..7
    const int y0 = wid * 8;
    const float cx0 = (float)(16 * lane + 4);
    const float cx1 = cx0 + 8.0f;

    float2 b2[8], zb2[8], sb2[8];
    #pragma unroll
    for (int t = 0; t < 8; t++) {
        int idx = (y0 + t) * 32 + lane;
        float2 b = bp2[idx];
        b2[t] = b;
        zb2[t] = make_float2(__logf(b.x), __logf(b.y));
        sb2[t] = make_float2(0.0f, 0.0f);
    }

    if (tid < NIT) {
        uint32_t c0 = 0u, c1 = 1u;
        tf2x32(0u, 1u, c0, c1);               // k2
        uint32_t x0 = 0u, x1 = (uint32_t)(s * NIT + tid);
        tf2x32(c0, c1, x0, x1);
        int i = (int)((x0 ^ x1) & 511u);
        SPT[tid] = make_float2(pp[2 * i], pp[2 * i + 1]);
        SCK[tid] = __fdividef(512.0f, sqrtf((float)(tid + 1)));   // ck/10
    }
    __syncthreads();

    for (int k = 0; k < NIT; k++) {
        float2 p = SPT[k];
        float ck10 = SCK[k];
        float dx0 = p.x - cx0, dx1 = p.x - cx1;
        float dq0 = dx0 * dx0 * 0.1f;
        float dq1 = dx1 * dx1 * 0.1f;

        // ---- Phase A: z + block max (no MUFU) ----
        float z0[8], z1[8];
        float mx = -INFINITY;
        #pragma unroll
        for (int t = 0; t < 8; t++) {
            float dy = p.y - (float)((y0 + t) * 8 + 4);
            float dyq = dy * dy * 0.1f;
            z0[t] = zb2[t].x - dq0 - dyq;
            z1[t] = zb2[t].y - dq1 - dyq;
            mx = fmaxf(mx, fmaxf(z0[t], z1[t]));
        }
        #pragma unroll
        for (int o = 16; o > 0; o >>= 1)
            mx = fmaxf(mx, __shfl_xor_sync(0xffffffffu, mx, o));
        if (lane == 0) SMX[wid] = mx;
        __syncthreads();
        float4 ma = *(const float4*)SMX;
        float4 mb = *(const float4*)(SMX + 4);
        float gm = fmaxf(fmaxf(fmaxf(ma.x, ma.y), fmaxf(ma.z, ma.w)),
                         fmaxf(fmaxf(mb.x, mb.y), fmaxf(mb.z, mb.w)));

        // ---- Phase B: per-warp skip or exp; block sum ----
        bool active = (mx >= gm - 88.0f);     // mx = this warp's slab max
        float e0[8], e1[8];
        float se = 0.0f;
        if (active) {
            #pragma unroll
            for (int t = 0; t < 8; t++) {
                e0[t] = exp2f((z0[t] - gm) * L2E);
                e1[t] = exp2f((z1[t] - gm) * L2E);
                se += e0[t] + e1[t];
            }
        }
        #pragma unroll
        for (int o = 16; o > 0; o >>= 1)
            se += __shfl_xor_sync(0xffffffffu, se, o);
        if (lane == 0) SSM[wid] = se;
        __syncthreads();
        float4 sa = *(const float4*)SSM;
        float4 sb4 = *(const float4*)(SSM + 4);
        float bs = ((sa.x + sa.y) + (sa.z + sa.w))
                 + ((sb4.x + sb4.y) + (sb4.z + sb4.w));

        // ---- Update ----
        float a = ck10 * __fdividef(1.0f, bs);
        if (active) {
            #pragma unroll
            for (int t = 0; t < 8; t++) {
                zb2[t].x = fmaf(-a, e0[t], fmaf(ck10, b2[t].x, zb2[t].x));
                zb2[t].y = fmaf(-a, e1[t], fmaf(ck10, b2[t].y, zb2[t].y));
                sb2[t].x += zb2[t].x;
                sb2[t].y += zb2[t].y;
            }
        } else {
            #pragma unroll
            for (int t = 0; t < 8; t++) {
                zb2[t].x = fmaf(ck10, b2[t].x, zb2[t].x);
                zb2[t].y = fmaf(ck10, b2[t].y, zb2[t].y);
                sb2[t].x += zb2[t].x;
                sb2[t].y += zb2[t].y;
            }
        }
    }

    // ---- Epilogue: w = 0.1*sb; ave = w - 10*lb; reductions ----
    float aveR[16], srcR[16];
    float p_ot = 0.0f, p_sc = 0.0f, p_td = 0.0f, wmx = -INFINITY;
    #pragma unroll
    for (int t = 0; t < 8; t++) {
        int jj = (y0 + t) * 64 + 2 * lane;
        float wA = 0.1f * sb2[t].x;
        float wB = 0.1f * sb2[t].y;
        float aveA = wA - 10.0f * __logf(b2[t].x);
        float aveB = wB - 10.0f * __logf(b2[t].y);
        g_w[s * MS + jj]     = wA;
        g_w[s * MS + jj + 1] = wB;
        float srcA = up[jj], srcB = up[jj + 1];
        aveR[2*t] = aveA; aveR[2*t+1] = aveB;
        srcR[2*t] = srcA; srcR[2*t+1] = srcB;
        p_ot += b2[t].x * aveA + b2[t].y * aveB;
        p_sc += srcA + srcB;
        p_td += srcA * aveA + srcB * aveB;
        wmx = fmaxf(wmx, fmaxf(wA, wB));
    }
    float ot = blk_red8(p_ot, SRED, 0);
    float sc = blk_red8(p_sc, SRED, 0);
    float td = blk_red8(p_td, SRED, 0);
    float wm = blk_red8(wmx, SRED, 1);
    float denom = sc * sc + 1e-16f;
    float q1s = sc / denom, q2s = td / denom;
    float p_ls = 0.0f;
    #pragma unroll
    for (int t = 0; t < 16; t++) p_ls += srcR[t] * (q1s * aveR[t] - q2s);
    float ls = blk_red8(p_ls, SRED, 0);
    if (tid == 0) {
        g_ot[s] = ot;
        g_loss[s] = ls;
        g_wmax[s] = wm;
        if (s == 0) g_ctr = 0;
    }
}

// ---------------------------------------------------------------------------
// wd kernel (adaptive region, verified): per row i, softmax of (w - M)/10;
// stabilizer anchored at own cell with wmax guard; region M <= D10 + 350.
// grid (32 chunks, 16 samples) = 512 blocks, 256 threads, warp = 2 rows.
// Last block performs the deterministic finalize.
// ---------------------------------------------------------------------------
__global__ void __launch_bounds__(256)
k_wd(const float* __restrict__ pts, float* __restrict__ out) {
    const int s = blockIdx.y;
    const int chunk = blockIdx.x;
    const int tid = threadIdx.x;
    const int wid = tid >> 5, lane = tid & 31;
    __shared__ float sw[MS];
    __shared__ float wacc[8];
    __shared__ unsigned int sflag;

    for (int j = tid; j < MS; j += 256)
        sw[j] = g_w[s * MS + j];
    const float wmax = g_wmax[s];
    __syncthreads();

    const float* pp = pts + s * NPTS * 2;
    float acc = 0.0f;

    #pragma unroll
    for (int rr = 0; rr < 2; rr++) {
        int i = chunk * 16 + wid * 2 + rr;
        float px = pp[2 * i], py = pp[2 * i + 1];

        int jxs = (int)(px * 0.125f);
        int jys = (int)(py * 0.125f);
        int js  = jys * 64 + jxs;
        float dxs = px - (float)(jxs * 8 + 4);
        float dys = py - (float)(jys * 8 + 4);
        float Ms  = dxs * dxs + dys * dys;
        float raws = sw[js] - Ms;              // raw units
        float D10 = wmax - raws;
        float m = raws * 0.1f + fmaxf(0.0f, D10 * 0.1f - 70.0f);
        float T = fmaxf(D10, 0.0f) + 350.0f;
        float xr = sqrtf(T);
        int jxlo = max(0,  (int)ceilf ((px - xr - 4.0f) * 0.125f));
        int jxhi = min(63, (int)floorf((px + xr - 4.0f) * 0.125f));
        int jylo = max(0,  (int)ceilf ((py - xr - 4.0f) * 0.125f));
        int jyhi = min(63, (int)floorf((py + xr - 4.0f) * 0.125f));

        float se = 0.0f, st = 0.0f;
        for (int jy = jylo; jy <= jyhi; jy++) {
            float dy = py - (float)(jy * 8 + 4);
            float yd = dy * dy;
            for (int jx = jxlo + lane; jx <= jxhi; jx += 32) {
                float dx = px - (float)(jx * 8 + 4);
                float M = yd + dx * dx;
                int j = jy * 64 + jx;
                float e = __expf((sw[j] - M) * 0.1f - m);
                se += e;
                st += e * M;
            }
        }
        #pragma unroll
        for (int o = 16; o > 0; o >>= 1) {
            se += __shfl_xor_sync(0xffffffffu, se, o);
            st += __shfl_xor_sync(0xffffffffu, st, o);
        }
        se = fmaxf(se, 1e-30f);
        acc += st / se;
    }
    if (lane == 0) wacc[wid] = acc;
    __syncthreads();
    if (tid == 0) {
        float t = 0.0f;
        #pragma unroll
        for (int w = 0; w < 8; w++) t += wacc[w];
        g_wd[s * NCH + chunk] = t * (1.0f / 512.0f);
        __threadfence();
        unsigned int old = atomicAdd(&g_ctr, 1u);
        sflag = (old == (NB * NCH - 1)) ? 1u : 0u;
    }
    __syncthreads();

    // ---- Fused finalize by the last block (fixed-order: deterministic) ----
    if (sflag) {
        float v = g_wd[tid] + g_wd[tid + 256];
        #pragma unroll
        for (int o = 16; o > 0; o >>= 1)
            v += __shfl_xor_sync(0xffffffffu, v, o);
        if (lane == 0) wacc[wid] = v;
        __syncthreads();
        if (tid == 0) {
            float W = 0.0f;
            #pragma unroll
            for (int w = 0; w < 8; w++) W += wacc[w];
            float L = 0.0f, O = 0.0f;
            for (int q = 0; q < NB; q++) { L += g_loss[q]; O += g_ot[q]; }
            out[0] = L; out[1] = W; out[2] = O;
        }
    }
}

extern "C" void kernel_launch(void* const* d_in, const int* in_sizes, int n_in,
                              void* d_out, int out_size) {
    const float* normed   = (const float*)d_in[0];
    const float* unnormed = (const float*)d_in[1];
    const float* pts      = (const float*)d_in[2];
    float* out = (float*)d_out;

    k_scan<<<NB, 256>>>(normed, unnormed, pts);
    dim3 g(NCH, NB);
    k_wd<<<g, 256>>>(pts, out);
}